// round 8
// baseline (speedup 1.0000x reference)
#include <cuda_runtime.h>
#include <cuda_bf16.h>
#include <cstdint>

// EncoderGRU B=16384 T=512 I=4 H=64 — bf16 m16n8k16 mma.sync, register-resident h.
// 128 CTAs x 256 thr (8 warps = 2/SMSP). Warp owns 16 batches, ALL 64 units.
// Key: D-frag of unit-block j == A-frag slots of k-tile j/2 for the same thread,
// so the recurrence closes entirely in registers: epilogue -> hold[j][4] ->
// bsplit -> next A-frags. No smem h, no barriers in the hot loop.
// 3-term bf16 split (AhiBhi+AloBhi+AhiBlo), fp32 accum; x folded as one k16 tile.
// All gates via tanh.approx (sigmoid = 0.5*tanh(x/2)+0.5) -> 3 MUFU/element.

#define T_STEPS 512
#define THREADS 256

#define OFF_BB   0u        // ulonglong2[24 nt][4 kt][32]  49152
#define OFF_BX   49152u    // u64[16 nt][32]                4096
#define OFF_BXN  53248u    // u64[8 nt][32]                 2048
#define OFF_BRZ  55296u    // float[128]
#define OFF_BNH  55808u    // float[64]
#define OFF_BNX  56064u    // float[64]
#define SMEM_TOTAL 56320

#define LO32(u) ((uint32_t)(u))
#define HI32(u) ((uint32_t)((u) >> 32))

__device__ __forceinline__ uint32_t pkb(__nv_bfloat16 a, __nv_bfloat16 b) {
    return (uint32_t)*(uint16_t*)&a | ((uint32_t)*(uint16_t*)&b << 16);
}
__device__ __forceinline__ void bsplit2(float a, float b, uint32_t& hi, uint32_t& lo) {
    __nv_bfloat16 ah = __float2bfloat16_rn(a), bh = __float2bfloat16_rn(b);
    __nv_bfloat16 al = __float2bfloat16_rn(a - __bfloat162float(ah));
    __nv_bfloat16 bl = __float2bfloat16_rn(b - __bfloat162float(bh));
    hi = pkb(ah, bh);
    lo = pkb(al, bl);
}
__device__ __forceinline__ void mma16(float* d, const uint32_t* a, uint32_t b0, uint32_t b1) {
    asm("mma.sync.aligned.m16n8k16.row.col.f32.bf16.bf16.f32 "
        "{%0,%1,%2,%3}, {%4,%5,%6,%7}, {%8,%9}, {%0,%1,%2,%3};"
        : "+f"(d[0]), "+f"(d[1]), "+f"(d[2]), "+f"(d[3])
        : "r"(a[0]), "r"(a[1]), "r"(a[2]), "r"(a[3]), "r"(b0), "r"(b1));
}
__device__ __forceinline__ float tanh_apx(float v) {
    float y; asm("tanh.approx.f32 %0, %1;" : "=f"(y) : "f"(v)); return y;
}
__device__ __forceinline__ float sig_t(float v) {        // sigmoid via tanh: 1 MUFU
    return fmaf(tanh_apx(0.5f * v), 0.5f, 0.5f);
}

__global__ __launch_bounds__(THREADS, 1)
void gru_rmma(const float* __restrict__ x, const float* __restrict__ w_ih,
              const float* __restrict__ w_hh, const float* __restrict__ b_ih,
              const float* __restrict__ b_hh, float* __restrict__ out)
{
    extern __shared__ char sm[];
    ulonglong2* BB  = (ulonglong2*)(sm + OFF_BB);
    uint64_t*   BX  = (uint64_t*)(sm + OFF_BX);
    uint64_t*   BXN = (uint64_t*)(sm + OFF_BXN);
    float* BRZ = (float*)(sm + OFF_BRZ);
    float* BNH = (float*)(sm + OFF_BNH);
    float* BNX = (float*)(sm + OFF_BNX);

    const int tid = threadIdx.x, lane = tid & 31, warp = tid >> 5;

    // ================= one-time init =================
    // BB[nt][kt][lane]: .x = {Whi(k0,k0+1), Whi(k8,k8+1)}, .y = lo residuals.
    for (int idx = tid; idx < 24 * 4 * 32; idx += THREADS) {
        int nt = idx >> 7, kt = (idx >> 5) & 3, le = idx & 31;
        int n = nt * 8 + (le >> 2), k0 = kt * 16 + 2 * (le & 3);
        uint32_t h01, l01, h89, l89;
        bsplit2(w_hh[n * 64 + k0],     w_hh[n * 64 + k0 + 1], h01, l01);
        bsplit2(w_hh[n * 64 + k0 + 8], w_hh[n * 64 + k0 + 9], h89, l89);
        BB[idx].x = (uint64_t)h01 | ((uint64_t)h89 << 32);
        BB[idx].y = (uint64_t)l01 | ((uint64_t)l89 << 32);
    }
    // x-tile B (k16 rows = [Whi(4) | Whi dup(4) | Wlo(4) | 0(4)])
    for (int idx = tid; idx < 16 * 32; idx += THREADS) {
        int nt = idx >> 5, le = idx & 31, c = le & 3;
        int n = nt * 8 + (le >> 2), cc = 2 * (c & 1);
        uint32_t hi, lo;
        bsplit2(w_ih[n * 4 + cc], w_ih[n * 4 + cc + 1], hi, lo);
        BX[idx] = (uint64_t)hi | ((uint64_t)((c < 2) ? lo : 0u) << 32);
    }
    for (int idx = tid; idx < 8 * 32; idx += THREADS) {
        int nt = idx >> 5, le = idx & 31, c = le & 3;
        int n = 128 + nt * 8 + (le >> 2), cc = 2 * (c & 1);
        uint32_t hi, lo;
        bsplit2(w_ih[n * 4 + cc], w_ih[n * 4 + cc + 1], hi, lo);
        BXN[idx] = (uint64_t)hi | ((uint64_t)((c < 2) ? lo : 0u) << 32);
    }
    for (int idx = tid; idx < 128; idx += THREADS) BRZ[idx] = b_ih[idx] + b_hh[idx];
    if (tid < 64) { BNH[tid] = b_hh[128 + tid]; BNX[tid] = b_ih[128 + tid]; }
    __syncthreads();

    // ================= per-warp geometry =================
    const int base = (blockIdx.x * 8 + warp) * 16;
    const int g = lane >> 2, c = lane & 3;
    const int u0 = 2 * c, cc = 2 * (c & 1);

    const float* __restrict__ xr0 = x + ((size_t)(base + g) * T_STEPS) * 4 + cc;
    const float* __restrict__ xr8 = x + ((size_t)(base + g + 8) * T_STEPS) * 4 + cc;
    float2 xq0 = *(const float2*)xr0;
    float2 xq8 = *(const float2*)xr8;

    // hold[j][.]: h for units {j*8+u0, j*8+u0+1} at rows g (0,1) and g+8 (2,3)
    float hold[8][4];
#pragma unroll
    for (int j = 0; j < 8; j++)
#pragma unroll
        for (int e = 0; e < 4; e++) hold[j][e] = 0.0f;

    uint32_t Ahi[4][4], Alo[4][4], Ax[4];
#pragma unroll
    for (int kt = 0; kt < 4; kt++)
#pragma unroll
        for (int e = 0; e < 4; e++) { Ahi[kt][e] = 0u; Alo[kt][e] = 0u; }

    for (int t = 0; t < T_STEPS; t++) {
        // ---- x frag: A cols [xhi(4)|xlo(4)|xhi(4)|0(4)] ----
        {
            uint32_t xh0, xl0, xh8, xl8;
            bsplit2(xq0.x, xq0.y, xh0, xl0);
            bsplit2(xq8.x, xq8.y, xh8, xl8);
            Ax[0] = (c < 2) ? xh0 : xl0;
            Ax[1] = (c < 2) ? xh8 : xl8;
            Ax[2] = (c < 2) ? xh0 : 0u;
            Ax[3] = (c < 2) ? xh8 : 0u;
        }
        if (t + 1 < T_STEPS) {   // prefetch under MMA latency
            xq0 = *(const float2*)(xr0 + (size_t)(t + 1) * 4);
            xq8 = *(const float2*)(xr8 + (size_t)(t + 1) * 4);
        }

        // ---- unit-blocks in pairs: 8 accumulator chains in flight ----
#pragma unroll 1
        for (int jp = 0; jp < 4; jp++) {
            float dr[2][4] = {}, dz[2][4] = {}, dn[2][4] = {}, dx[2][4] = {};
#pragma unroll
            for (int kt = 0; kt < 4; kt++) {
#pragma unroll
                for (int s = 0; s < 2; s++) {
                    const int j = 2 * jp + s;
                    ulonglong2 br = BB[(j * 4 + kt) * 32 + lane];
                    ulonglong2 bz = BB[((8 + j) * 4 + kt) * 32 + lane];
                    ulonglong2 bn = BB[((16 + j) * 4 + kt) * 32 + lane];
                    mma16(dr[s], Ahi[kt], LO32(br.x), HI32(br.x));
                    mma16(dz[s], Ahi[kt], LO32(bz.x), HI32(bz.x));
                    mma16(dn[s], Ahi[kt], LO32(bn.x), HI32(bn.x));
                    mma16(dr[s], Alo[kt], LO32(br.x), HI32(br.x));
                    mma16(dz[s], Alo[kt], LO32(bz.x), HI32(bz.x));
                    mma16(dn[s], Alo[kt], LO32(bn.x), HI32(bn.x));
                    mma16(dr[s], Ahi[kt], LO32(br.y), HI32(br.y));
                    mma16(dz[s], Ahi[kt], LO32(bz.y), HI32(bz.y));
                    mma16(dn[s], Ahi[kt], LO32(bn.y), HI32(bn.y));
                }
            }
#pragma unroll
            for (int s = 0; s < 2; s++) {
                const int j = 2 * jp + s;
                uint64_t bxr = BX[j * 32 + lane];
                uint64_t bxz = BX[(8 + j) * 32 + lane];
                uint64_t bxn = BXN[j * 32 + lane];
                mma16(dr[s], Ax, LO32(bxr), HI32(bxr));
                mma16(dz[s], Ax, LO32(bxz), HI32(bxz));
                mma16(dx[s], Ax, LO32(bxn), HI32(bxn));
            }
            // ---- epilogue for both j's (in-place hold update) ----
#pragma unroll
            for (int s = 0; s < 2; s++) {
                const int j = 2 * jp + s;
                float2 b_r = *(const float2*)(BRZ + j * 8 + u0);
                float2 b_z = *(const float2*)(BRZ + 64 + j * 8 + u0);
                float2 b_h = *(const float2*)(BNH + j * 8 + u0);
                float2 b_x = *(const float2*)(BNX + j * 8 + u0);
#pragma unroll
                for (int e = 0; e < 4; e++) {
                    float brv = (e & 1) ? b_r.y : b_r.x;
                    float bzv = (e & 1) ? b_z.y : b_z.x;
                    float bhv = (e & 1) ? b_h.y : b_h.x;
                    float bxv = (e & 1) ? b_x.y : b_x.x;
                    float r = sig_t(dr[s][e] + brv);
                    float z = sig_t(dz[s][e] + bzv);
                    float n = tanh_apx(fmaf(r, dn[s][e] + bhv, dx[s][e] + bxv));
                    hold[j][e] = fmaf(z, hold[j][e] - n, n);
                }
            }
        }

        // ---- rebuild A frags from hold (register-only; no smem) ----
        if (t + 1 < T_STEPS) {
#pragma unroll
            for (int kt = 0; kt < 4; kt++) {
                bsplit2(hold[2 * kt][0],     hold[2 * kt][1],     Ahi[kt][0], Alo[kt][0]);
                bsplit2(hold[2 * kt][2],     hold[2 * kt][3],     Ahi[kt][1], Alo[kt][1]);
                bsplit2(hold[2 * kt + 1][0], hold[2 * kt + 1][1], Ahi[kt][2], Alo[kt][2]);
                bsplit2(hold[2 * kt + 1][2], hold[2 * kt + 1][3], Ahi[kt][3], Alo[kt][3]);
            }
        }
    }

    // ---- output: thread owns units {j*8+u0, +1} at rows g, g+8 ----
#pragma unroll
    for (int j = 0; j < 8; j++) {
        *(float2*)(out + (size_t)(base + g) * 64 + j * 8 + u0)     = make_float2(hold[j][0], hold[j][1]);
        *(float2*)(out + (size_t)(base + g + 8) * 64 + j * 8 + u0) = make_float2(hold[j][2], hold[j][3]);
    }
}

extern "C" void kernel_launch(void* const* d_in, const int* in_sizes, int n_in,
                              void* d_out, int out_size)
{
    const float* x    = (const float*)d_in[0];
    const float* w_ih = (const float*)d_in[1];
    const float* w_hh = (const float*)d_in[2];
    const float* b_ih = (const float*)d_in[3];
    const float* b_hh = (const float*)d_in[4];
    float* out = (float*)d_out;

    cudaFuncSetAttribute(gru_rmma, cudaFuncAttributeMaxDynamicSharedMemorySize, SMEM_TOTAL);
    gru_rmma<<<128, THREADS, SMEM_TOTAL>>>(x, w_ih, w_hh, b_ih, b_hh, out);
}

// round 9
// speedup vs baseline: 1.1748x; 1.1748x over previous
#include <cuda_runtime.h>
#include <cuda_fp16.h>
#include <cstdint>

// EncoderGRU B=16384 T=512 I=4 H=64 — fp16 m16n8k16 mma.sync, 2-term split.
// 128 CTAs x 512 thr (16 warps = 4/SMSP). Warp PAIR owns 16 batches; each warp
// handles half the units (j 0..3 / 4..7 => 108 MMAs/warp-step).
// Precision: h = h_hi + h_lo (fp16 pair, exact to 2^-22); preact = h x W_hi
// computed exactly in fp32 accum; dropped h x W_lo ~ 2^-12.5 relative.
// x folded as one k16 tile with full 3-term ([xhi|xlo|xhi|0] x [Whi|Whi|Wlo|0]).
// h double-buffered in smem; one named bar.sync(64) per pair per step.

#define T_STEPS 512
#define THREADS 512
#define HP 72   // h row stride (floats)

#define OFF_BB   0u        // u64[24 nt][4 kt][32]   24576  (W_hi frags only)
#define OFF_BX   24576u    // u64[16 nt][32]          4096
#define OFF_BXN  28672u    // u64[8 nt][32]           2048
#define OFF_HS   30720u    // float[8 pairs][2][16][HP] 73728
#define OFF_BRZ  104448u   // float[128]
#define OFF_BNH  104960u   // float[64]
#define OFF_BNX  105216u   // float[64]
#define SMEM_TOTAL 105472

#define LO32(u) ((uint32_t)(u))
#define HI32(u) ((uint32_t)((u) >> 32))

__device__ __forceinline__ uint32_t pkh(__half a, __half b) {
    return (uint32_t)*(uint16_t*)&a | ((uint32_t)*(uint16_t*)&b << 16);
}
// split (a,b) into packed fp16 hi pair + fp16 lo (residual) pair
__device__ __forceinline__ void hsplit2(float a, float b, uint32_t& hi, uint32_t& lo) {
    __half ah = __float2half_rn(a), bh = __float2half_rn(b);
    __half al = __float2half_rn(a - __half2float(ah));
    __half bl = __float2half_rn(b - __half2float(bh));
    hi = pkh(ah, bh);
    lo = pkh(al, bl);
}
__device__ __forceinline__ void mma16(float* d, const uint32_t* a, uint32_t b0, uint32_t b1) {
    asm("mma.sync.aligned.m16n8k16.row.col.f32.f16.f16.f32 "
        "{%0,%1,%2,%3}, {%4,%5,%6,%7}, {%8,%9}, {%0,%1,%2,%3};"
        : "+f"(d[0]), "+f"(d[1]), "+f"(d[2]), "+f"(d[3])
        : "r"(a[0]), "r"(a[1]), "r"(a[2]), "r"(a[3]), "r"(b0), "r"(b1));
}
__device__ __forceinline__ float sigf(float x) {
    return __fdividef(1.0f, 1.0f + __expf(-x));
}
__device__ __forceinline__ float tanhf_fast(float x) {
    return 1.0f - __fdividef(2.0f, __expf(2.0f * x) + 1.0f);
}

__global__ __launch_bounds__(THREADS, 1)
void gru_h2(const float* __restrict__ x, const float* __restrict__ w_ih,
            const float* __restrict__ w_hh, const float* __restrict__ b_ih,
            const float* __restrict__ b_hh, float* __restrict__ out)
{
    extern __shared__ char sm[];
    uint64_t* BB  = (uint64_t*)(sm + OFF_BB);
    uint64_t* BX  = (uint64_t*)(sm + OFF_BX);
    uint64_t* BXN = (uint64_t*)(sm + OFF_BXN);
    float* HS  = (float*)(sm + OFF_HS);
    float* BRZ = (float*)(sm + OFF_BRZ);
    float* BNH = (float*)(sm + OFF_BNH);
    float* BNX = (float*)(sm + OFF_BNX);

    const int tid = threadIdx.x, lane = tid & 31, warp = tid >> 5;

    // ================= one-time init =================
    // BB[nt][kt][lane] = {Whi(k0,k0+1), Whi(k8,k8+1)} for n = nt*8 + le/4,
    // k0 = kt*16 + 2*(le%4). fp16 hi only (2-term scheme).
    for (int idx = tid; idx < 24 * 4 * 32; idx += THREADS) {
        int nt = idx >> 7, kt = (idx >> 5) & 3, le = idx & 31;
        int n = nt * 8 + (le >> 2), k0 = kt * 16 + 2 * (le & 3);
        uint32_t h01, l01, h89, l89;
        hsplit2(w_hh[n * 64 + k0],     w_hh[n * 64 + k0 + 1], h01, l01);
        hsplit2(w_hh[n * 64 + k0 + 8], w_hh[n * 64 + k0 + 9], h89, l89);
        BB[idx] = (uint64_t)h01 | ((uint64_t)h89 << 32);
    }
    // x-tile B (k16 rows = [Whi(4) | Whi dup(4) | Wlo(4) | 0(4)]):
    for (int idx = tid; idx < 16 * 32; idx += THREADS) {
        int nt = idx >> 5, le = idx & 31, c = le & 3;
        int n = nt * 8 + (le >> 2), cc = 2 * (c & 1);
        uint32_t hi, lo;
        hsplit2(w_ih[n * 4 + cc], w_ih[n * 4 + cc + 1], hi, lo);
        BX[idx] = (uint64_t)hi | ((uint64_t)((c < 2) ? lo : 0u) << 32);
    }
    for (int idx = tid; idx < 8 * 32; idx += THREADS) {
        int nt = idx >> 5, le = idx & 31, c = le & 3;
        int n = 128 + nt * 8 + (le >> 2), cc = 2 * (c & 1);
        uint32_t hi, lo;
        hsplit2(w_ih[n * 4 + cc], w_ih[n * 4 + cc + 1], hi, lo);
        BXN[idx] = (uint64_t)hi | ((uint64_t)((c < 2) ? lo : 0u) << 32);
    }
    for (int idx = tid; idx < 8 * 2 * 16 * HP; idx += THREADS) HS[idx] = 0.0f;
    for (int idx = tid; idx < 128; idx += THREADS) BRZ[idx] = b_ih[idx] + b_hh[idx];
    if (tid < 64) { BNH[tid] = b_hh[128 + tid]; BNX[tid] = b_ih[128 + tid]; }
    __syncthreads();

    // ================= per-warp geometry =================
    const int pair = warp >> 1, half = warp & 1;
    const int base = (blockIdx.x * 8 + pair) * 16;
    float* hs0 = HS + pair * (2 * 16 * HP);
    const int g = lane >> 2, c = lane & 3;
    const int u0 = 2 * c, cc = 2 * (c & 1);
    const int j0 = half * 4;

    const float* __restrict__ xr0 = x + ((size_t)(base + g) * T_STEPS) * 4 + cc;
    const float* __restrict__ xr8 = x + ((size_t)(base + g + 8) * T_STEPS) * 4 + cc;
    float2 xq0 = *(const float2*)xr0;
    float2 xq8 = *(const float2*)xr8;

    uint32_t Ahi[4][4], Alo[4][4], Ax[4];

    for (int t = 0; t < T_STEPS; t++) {
        float* hrd = hs0 + (t & 1) * (16 * HP);
        float* hwr = hs0 + ((t & 1) ^ 1) * (16 * HP);

        // ---- A frags from h smem (both warps duplicate; cheap) ----
#pragma unroll
        for (int kt = 0; kt < 4; kt++) {
            const float* r0 = hrd + g * HP + kt * 16 + u0;
            const float* r8 = r0 + 8 * HP;
            float2 v0 = *(const float2*)r0;
            float2 v8 = *(const float2*)r8;
            float2 w0 = *(const float2*)(r0 + 8);
            float2 w8 = *(const float2*)(r8 + 8);
            hsplit2(v0.x, v0.y, Ahi[kt][0], Alo[kt][0]);
            hsplit2(v8.x, v8.y, Ahi[kt][1], Alo[kt][1]);
            hsplit2(w0.x, w0.y, Ahi[kt][2], Alo[kt][2]);
            hsplit2(w8.x, w8.y, Ahi[kt][3], Alo[kt][3]);
        }
        {   // x frag: A cols [xhi(4)|xlo(4)|xhi(4)|0(4)]
            uint32_t xh0, xl0, xh8, xl8;
            hsplit2(xq0.x, xq0.y, xh0, xl0);
            hsplit2(xq8.x, xq8.y, xh8, xl8);
            Ax[0] = (c < 2) ? xh0 : xl0;
            Ax[1] = (c < 2) ? xh8 : xl8;
            Ax[2] = (c < 2) ? xh0 : 0u;
            Ax[3] = (c < 2) ? xh8 : 0u;
        }
        if (t + 1 < T_STEPS) {   // prefetch under MMA latency
            xq0 = *(const float2*)(xr0 + (size_t)(t + 1) * 4);
            xq8 = *(const float2*)(xr8 + (size_t)(t + 1) * 4);
        }

        // ---- this warp's 4 unit-blocks: 2 terms per gate (h x W_hi exact) ----
#pragma unroll 1
        for (int jj = 0; jj < 4; jj++) {
            const int j = j0 + jj;
            float dr[4] = {}, dz[4] = {}, dn[4] = {}, dx[4] = {};
#pragma unroll
            for (int kt = 0; kt < 4; kt++) {
                uint64_t br = BB[(j * 4 + kt) * 32 + lane];
                uint64_t bz = BB[((8 + j) * 4 + kt) * 32 + lane];
                uint64_t bn = BB[((16 + j) * 4 + kt) * 32 + lane];
                mma16(dr, Ahi[kt], LO32(br), HI32(br));
                mma16(dz, Ahi[kt], LO32(bz), HI32(bz));
                mma16(dn, Ahi[kt], LO32(bn), HI32(bn));
                mma16(dr, Alo[kt], LO32(br), HI32(br));
                mma16(dz, Alo[kt], LO32(bz), HI32(bz));
                mma16(dn, Alo[kt], LO32(bn), HI32(bn));
            }
            {
                uint64_t bxr = BX[j * 32 + lane];
                uint64_t bxz = BX[(8 + j) * 32 + lane];
                uint64_t bxn = BXN[j * 32 + lane];
                mma16(dr, Ax, LO32(bxr), HI32(bxr));
                mma16(dz, Ax, LO32(bxz), HI32(bxz));
                mma16(dx, Ax, LO32(bxn), HI32(bxn));
            }
            // ---- epilogue: units j*8+u0, +1; rows g, g+8 ----
            float2 b_r = *(const float2*)(BRZ + j * 8 + u0);
            float2 b_z = *(const float2*)(BRZ + 64 + j * 8 + u0);
            float2 b_h = *(const float2*)(BNH + j * 8 + u0);
            float2 b_x = *(const float2*)(BNX + j * 8 + u0);
            const float* ha = hrd + g * HP + j * 8 + u0;
            const float* hb = ha + 8 * HP;
            float2 hoa = *(const float2*)ha;
            float2 hob = *(const float2*)hb;
            float hn0, hn1, hn2, hn3;
            {
                float r = sigf(dr[0] + b_r.x), z = sigf(dz[0] + b_z.x);
                float n = tanhf_fast(fmaf(r, dn[0] + b_h.x, dx[0] + b_x.x));
                hn0 = fmaf(z, hoa.x - n, n);
            }
            {
                float r = sigf(dr[1] + b_r.y), z = sigf(dz[1] + b_z.y);
                float n = tanhf_fast(fmaf(r, dn[1] + b_h.y, dx[1] + b_x.y));
                hn1 = fmaf(z, hoa.y - n, n);
            }
            {
                float r = sigf(dr[2] + b_r.x), z = sigf(dz[2] + b_z.x);
                float n = tanhf_fast(fmaf(r, dn[2] + b_h.x, dx[2] + b_x.x));
                hn2 = fmaf(z, hob.x - n, n);
            }
            {
                float r = sigf(dr[3] + b_r.y), z = sigf(dz[3] + b_z.y);
                float n = tanhf_fast(fmaf(r, dn[3] + b_h.y, dx[3] + b_x.y));
                hn3 = fmaf(z, hob.y - n, n);
            }
            float* wa = hwr + g * HP + j * 8 + u0;
            *(float2*)wa            = make_float2(hn0, hn1);
            *(float2*)(wa + 8 * HP) = make_float2(hn2, hn3);
        }

        // pair-scoped barrier: this step's h' writes before next step's reads
        asm volatile("bar.sync %0, %1;" :: "r"(pair + 1), "r"(64) : "memory");
    }

    // ---- output ----
    const float* hfin = hs0 + (T_STEPS & 1) * (16 * HP);
    for (int idx = lane; idx < 16 * 8; idx += 32) {
        int b = idx >> 3, q = idx & 7;
        float4 v = *(const float4*)(hfin + b * HP + half * 32 + q * 4);
        ((float4*)out)[(size_t)(base + b) * 16 + half * 8 + q] = v;
    }
}

extern "C" void kernel_launch(void* const* d_in, const int* in_sizes, int n_in,
                              void* d_out, int out_size)
{
    const float* x    = (const float*)d_in[0];
    const float* w_ih = (const float*)d_in[1];
    const float* w_hh = (const float*)d_in[2];
    const float* b_ih = (const float*)d_in[3];
    const float* b_hh = (const float*)d_in[4];
    float* out = (float*)d_out;

    cudaFuncSetAttribute(gru_h2, cudaFuncAttributeMaxDynamicSharedMemorySize, SMEM_TOTAL);
    gru_h2<<<128, THREADS, SMEM_TOTAL>>>(x, w_ih, w_hh, b_ih, b_hh, out);
}

// round 10
// speedup vs baseline: 2.1829x; 1.8581x over previous
#include <cuda_runtime.h>
#include <cuda_fp16.h>
#include <cstdint>

// EncoderGRU B=16384 T=512 I=4 H=64 — fp16 m16n8k16 mma.sync, 1-term h-path.
// 128 CTAs x 512 thr (16 warps = 4/SMSP). Warp PAIR owns 16 batches; each warp
// handles half the units (j 0..3 / 4..7 => 60 MMAs/warp-step).
// Precision: h_hi (fp16) x W_hi (fp16), fp32 accum; dropped h_lo*W_hi and
// h*W_lo terms each ~2^-11 relative (evidence-calibrated final ~1e-4).
// x folded as one k16 tile with full 3-term ([xhi|xlo|xhi|0] x [Whi|Whi|Wlo|0]).
// Gates via tanh.approx (3 MUFU/element). h double-buffered in smem; one named
// bar.sync(64) per pair per step.

#define T_STEPS 512
#define THREADS 512
#define HP 72   // h row stride (floats)

#define OFF_BB   0u        // u64[24 nt][4 kt][32]   24576  (W_hi frags only)
#define OFF_BX   24576u    // u64[16 nt][32]          4096
#define OFF_BXN  28672u    // u64[8 nt][32]           2048
#define OFF_HS   30720u    // float[8 pairs][2][16][HP] 73728
#define OFF_BRZ  104448u   // float[128]
#define OFF_BNH  104960u   // float[64]
#define OFF_BNX  105216u   // float[64]
#define SMEM_TOTAL 105472

#define LO32(u) ((uint32_t)(u))
#define HI32(u) ((uint32_t)((u) >> 32))

__device__ __forceinline__ uint32_t pkh(__half a, __half b) {
    return (uint32_t)*(uint16_t*)&a | ((uint32_t)*(uint16_t*)&b << 16);
}
__device__ __forceinline__ void hsplit2(float a, float b, uint32_t& hi, uint32_t& lo) {
    __half ah = __float2half_rn(a), bh = __float2half_rn(b);
    __half al = __float2half_rn(a - __half2float(ah));
    __half bl = __float2half_rn(b - __half2float(bh));
    hi = pkh(ah, bh);
    lo = pkh(al, bl);
}
__device__ __forceinline__ uint32_t hpack2(float a, float b) {   // cvt only (1-term A)
    __half2 h2 = __floats2half2_rn(a, b);
    return *(uint32_t*)&h2;
}
__device__ __forceinline__ void mma16(float* d, const uint32_t* a, uint32_t b0, uint32_t b1) {
    asm("mma.sync.aligned.m16n8k16.row.col.f32.f16.f16.f32 "
        "{%0,%1,%2,%3}, {%4,%5,%6,%7}, {%8,%9}, {%0,%1,%2,%3};"
        : "+f"(d[0]), "+f"(d[1]), "+f"(d[2]), "+f"(d[3])
        : "r"(a[0]), "r"(a[1]), "r"(a[2]), "r"(a[3]), "r"(b0), "r"(b1));
}
__device__ __forceinline__ float tanh_apx(float v) {
    float y; asm("tanh.approx.f32 %0, %1;" : "=f"(y) : "f"(v)); return y;
}
__device__ __forceinline__ float sig_t(float v) {   // sigmoid via tanh: 1 MUFU
    return fmaf(tanh_apx(0.5f * v), 0.5f, 0.5f);
}

__global__ __launch_bounds__(THREADS, 1)
void gru_h1(const float* __restrict__ x, const float* __restrict__ w_ih,
            const float* __restrict__ w_hh, const float* __restrict__ b_ih,
            const float* __restrict__ b_hh, float* __restrict__ out)
{
    extern __shared__ char sm[];
    uint64_t* BB  = (uint64_t*)(sm + OFF_BB);
    uint64_t* BX  = (uint64_t*)(sm + OFF_BX);
    uint64_t* BXN = (uint64_t*)(sm + OFF_BXN);
    float* HS  = (float*)(sm + OFF_HS);
    float* BRZ = (float*)(sm + OFF_BRZ);
    float* BNH = (float*)(sm + OFF_BNH);
    float* BNX = (float*)(sm + OFF_BNX);

    const int tid = threadIdx.x, lane = tid & 31, warp = tid >> 5;

    // ================= one-time init =================
    for (int idx = tid; idx < 24 * 4 * 32; idx += THREADS) {
        int nt = idx >> 7, kt = (idx >> 5) & 3, le = idx & 31;
        int n = nt * 8 + (le >> 2), k0 = kt * 16 + 2 * (le & 3);
        uint32_t h01, l01, h89, l89;
        hsplit2(w_hh[n * 64 + k0],     w_hh[n * 64 + k0 + 1], h01, l01);
        hsplit2(w_hh[n * 64 + k0 + 8], w_hh[n * 64 + k0 + 9], h89, l89);
        BB[idx] = (uint64_t)h01 | ((uint64_t)h89 << 32);
    }
    for (int idx = tid; idx < 16 * 32; idx += THREADS) {
        int nt = idx >> 5, le = idx & 31, c = le & 3;
        int n = nt * 8 + (le >> 2), cc = 2 * (c & 1);
        uint32_t hi, lo;
        hsplit2(w_ih[n * 4 + cc], w_ih[n * 4 + cc + 1], hi, lo);
        BX[idx] = (uint64_t)hi | ((uint64_t)((c < 2) ? lo : 0u) << 32);
    }
    for (int idx = tid; idx < 8 * 32; idx += THREADS) {
        int nt = idx >> 5, le = idx & 31, c = le & 3;
        int n = 128 + nt * 8 + (le >> 2), cc = 2 * (c & 1);
        uint32_t hi, lo;
        hsplit2(w_ih[n * 4 + cc], w_ih[n * 4 + cc + 1], hi, lo);
        BXN[idx] = (uint64_t)hi | ((uint64_t)((c < 2) ? lo : 0u) << 32);
    }
    for (int idx = tid; idx < 8 * 2 * 16 * HP; idx += THREADS) HS[idx] = 0.0f;
    for (int idx = tid; idx < 128; idx += THREADS) BRZ[idx] = b_ih[idx] + b_hh[idx];
    if (tid < 64) { BNH[tid] = b_hh[128 + tid]; BNX[tid] = b_ih[128 + tid]; }
    __syncthreads();

    // ================= per-warp geometry =================
    const int pair = warp >> 1, half = warp & 1;
    const int base = (blockIdx.x * 8 + pair) * 16;
    float* hs0 = HS + pair * (2 * 16 * HP);
    const int g = lane >> 2, c = lane & 3;
    const int u0 = 2 * c, cc = 2 * (c & 1);
    const int j0 = half * 4;

    const float* __restrict__ xr0 = x + ((size_t)(base + g) * T_STEPS) * 4 + cc;
    const float* __restrict__ xr8 = x + ((size_t)(base + g + 8) * T_STEPS) * 4 + cc;
    float2 xq0 = *(const float2*)xr0;
    float2 xq8 = *(const float2*)xr8;

    uint32_t Ahi[4][4], Ax[4];

    for (int t = 0; t < T_STEPS; t++) {
        float* hrd = hs0 + (t & 1) * (16 * HP);
        float* hwr = hs0 + ((t & 1) ^ 1) * (16 * HP);

        // ---- A frags from h smem: plain fp16 cvt (1-term) ----
#pragma unroll
        for (int kt = 0; kt < 4; kt++) {
            const float* r0 = hrd + g * HP + kt * 16 + u0;
            const float* r8 = r0 + 8 * HP;
            float2 v0 = *(const float2*)r0;
            float2 v8 = *(const float2*)r8;
            float2 w0 = *(const float2*)(r0 + 8);
            float2 w8 = *(const float2*)(r8 + 8);
            Ahi[kt][0] = hpack2(v0.x, v0.y);
            Ahi[kt][1] = hpack2(v8.x, v8.y);
            Ahi[kt][2] = hpack2(w0.x, w0.y);
            Ahi[kt][3] = hpack2(w8.x, w8.y);
        }
        {   // x frag: A cols [xhi(4)|xlo(4)|xhi(4)|0(4)]  (full 3-term for x)
            uint32_t xh0, xl0, xh8, xl8;
            hsplit2(xq0.x, xq0.y, xh0, xl0);
            hsplit2(xq8.x, xq8.y, xh8, xl8);
            Ax[0] = (c < 2) ? xh0 : xl0;
            Ax[1] = (c < 2) ? xh8 : xl8;
            Ax[2] = (c < 2) ? xh0 : 0u;
            Ax[3] = (c < 2) ? xh8 : 0u;
        }
        if (t + 1 < T_STEPS) {   // prefetch under MMA latency
            xq0 = *(const float2*)(xr0 + (size_t)(t + 1) * 4);
            xq8 = *(const float2*)(xr8 + (size_t)(t + 1) * 4);
        }

        // ---- 4 unit-blocks in 2 pairs: 8 accumulator chains in flight ----
#pragma unroll 1
        for (int jp = 0; jp < 2; jp++) {
            float dr[2][4] = {}, dz[2][4] = {}, dn[2][4] = {}, dx[2][4] = {};
#pragma unroll
            for (int kt = 0; kt < 4; kt++) {
#pragma unroll
                for (int s = 0; s < 2; s++) {
                    const int j = j0 + 2 * jp + s;
                    uint64_t br = BB[(j * 4 + kt) * 32 + lane];
                    uint64_t bz = BB[((8 + j) * 4 + kt) * 32 + lane];
                    uint64_t bn = BB[((16 + j) * 4 + kt) * 32 + lane];
                    mma16(dr[s], Ahi[kt], LO32(br), HI32(br));
                    mma16(dz[s], Ahi[kt], LO32(bz), HI32(bz));
                    mma16(dn[s], Ahi[kt], LO32(bn), HI32(bn));
                }
            }
#pragma unroll
            for (int s = 0; s < 2; s++) {
                const int j = j0 + 2 * jp + s;
                uint64_t bxr = BX[j * 32 + lane];
                uint64_t bxz = BX[(8 + j) * 32 + lane];
                uint64_t bxn = BXN[j * 32 + lane];
                mma16(dr[s], Ax, LO32(bxr), HI32(bxr));
                mma16(dz[s], Ax, LO32(bxz), HI32(bxz));
                mma16(dx[s], Ax, LO32(bxn), HI32(bxn));
            }
            // ---- epilogue for both j's ----
#pragma unroll
            for (int s = 0; s < 2; s++) {
                const int j = j0 + 2 * jp + s;
                float2 b_r = *(const float2*)(BRZ + j * 8 + u0);
                float2 b_z = *(const float2*)(BRZ + 64 + j * 8 + u0);
                float2 b_h = *(const float2*)(BNH + j * 8 + u0);
                float2 b_x = *(const float2*)(BNX + j * 8 + u0);
                const float* ha = hrd + g * HP + j * 8 + u0;
                const float* hb = ha + 8 * HP;
                float2 hoa = *(const float2*)ha;
                float2 hob = *(const float2*)hb;
                float hn0, hn1, hn2, hn3;
                {
                    float r = sig_t(dr[s][0] + b_r.x), z = sig_t(dz[s][0] + b_z.x);
                    float n = tanh_apx(fmaf(r, dn[s][0] + b_h.x, dx[s][0] + b_x.x));
                    hn0 = fmaf(z, hoa.x - n, n);
                }
                {
                    float r = sig_t(dr[s][1] + b_r.y), z = sig_t(dz[s][1] + b_z.y);
                    float n = tanh_apx(fmaf(r, dn[s][1] + b_h.y, dx[s][1] + b_x.y));
                    hn1 = fmaf(z, hoa.y - n, n);
                }
                {
                    float r = sig_t(dr[s][2] + b_r.x), z = sig_t(dz[s][2] + b_z.x);
                    float n = tanh_apx(fmaf(r, dn[s][2] + b_h.x, dx[s][2] + b_x.x));
                    hn2 = fmaf(z, hob.x - n, n);
                }
                {
                    float r = sig_t(dr[s][3] + b_r.y), z = sig_t(dz[s][3] + b_z.y);
                    float n = tanh_apx(fmaf(r, dn[s][3] + b_h.y, dx[s][3] + b_x.y));
                    hn3 = fmaf(z, hob.y - n, n);
                }
                float* wa = hwr + g * HP + j * 8 + u0;
                *(float2*)wa            = make_float2(hn0, hn1);
                *(float2*)(wa + 8 * HP) = make_float2(hn2, hn3);
            }
        }

        // pair-scoped barrier: this step's h' writes before next step's reads
        asm volatile("bar.sync %0, %1;" :: "r"(pair + 1), "r"(64) : "memory");
    }

    // ---- output ----
    const float* hfin = hs0 + (T_STEPS & 1) * (16 * HP);
    for (int idx = lane; idx < 16 * 8; idx += 32) {
        int b = idx >> 3, q = idx & 7;
        float4 v = *(const float4*)(hfin + b * HP + half * 32 + q * 4);
        ((float4*)out)[(size_t)(base + b) * 16 + half * 8 + q] = v;
    }
}

extern "C" void kernel_launch(void* const* d_in, const int* in_sizes, int n_in,
                              void* d_out, int out_size)
{
    const float* x    = (const float*)d_in[0];
    const float* w_ih = (const float*)d_in[1];
    const float* w_hh = (const float*)d_in[2];
    const float* b_ih = (const float*)d_in[3];
    const float* b_hh = (const float*)d_in[4];
    float* out = (float*)d_out;

    cudaFuncSetAttribute(gru_h1, cudaFuncAttributeMaxDynamicSharedMemorySize, SMEM_TOTAL);
    gru_h1<<<128, THREADS, SMEM_TOTAL>>>(x, w_ih, w_hh, b_ih, b_hh, out);
}